// round 3
// baseline (speedup 1.0000x reference)
#include <cuda_runtime.h>
#include <math.h>

#define BB 64
#define TT 4096
#define DD 128
#define HH 128
#define GG 384   // 3*H, gates packed [r, z, n]

typedef unsigned long long u64;

// Scratch (device globals — no allocation allowed in kernel_launch).
__device__ float g_gi[(size_t)TT * BB * GG];   // input-projection gates, [t][b][3H]
__device__ float g_h0[(size_t)TT * BB * HH];   // layer-0 hidden states,  [t][b][H]

// ---- packed f32x2 helpers ------------------------------------------------
__device__ __forceinline__ void fma2(u64& d, u64 a, u64 b) {
    asm("fma.rn.f32x2 %0, %1, %2, %0;" : "+l"(d) : "l"(a), "l"(b));
}
__device__ __forceinline__ u64 f2u(float x, float y) {
    u64 v; asm("mov.b64 %0, {%1,%2};" : "=l"(v) : "f"(x), "f"(y)); return v;
}
__device__ __forceinline__ float2 u2f(u64 v) {
    float2 r; asm("mov.b64 {%0,%1}, %2;" : "=f"(r.x), "=f"(r.y) : "l"(v)); return r;
}
__device__ __forceinline__ float hsum(u64 a, u64 b) {
    float2 x = u2f(a), y = u2f(b);
    return (x.x + x.y) + (y.x + y.y);
}
__device__ __forceinline__ float fsig(float x) {
    return __fdividef(1.0f, 1.0f + __expf(-x));
}
__device__ __forceinline__ float ftanh(float x) {
    // tanh(x) = 1 - 2/(exp(2x)+1); exact at both saturations.
    return 1.0f - __fdividef(2.0f, __expf(2.0f * x) + 1.0f);
}

// named-barrier primitives
__device__ __forceinline__ void bar_arrive(int id, int cnt) {
    asm volatile("bar.arrive %0, %1;" :: "r"(id), "r"(cnt) : "memory");
}
__device__ __forceinline__ void bar_sync(int id, int cnt) {
    asm volatile("bar.sync %0, %1;" :: "r"(id), "r"(cnt) : "memory");
}

// ---------------------------------------------------------------------------
// GEMM: g_gi[m][j] = dot(in_row(m), W[j]) + bias[j],  m = t*B + b
//   mode 0: input row = X + (b*T + t)*D   (x is [B,T,D])
//   mode 1: input row = g_h0 + m*H        (h0 is [T,B,H])
// ---------------------------------------------------------------------------
__global__ __launch_bounds__(384, 1) void gi_gemm(
    const float* __restrict__ X,
    const float* __restrict__ W,
    const float* __restrict__ bias,
    int mode)
{
    const int j = threadIdx.x;

    u64 w[64];
    {
        const ulonglong2* wr = (const ulonglong2*)(W + (size_t)j * 128);
        #pragma unroll
        for (int k = 0; k < 32; k++) { ulonglong2 v = wr[k]; w[2*k] = v.x; w[2*k+1] = v.y; }
    }
    const float bj = bias[j];

    __shared__ __align__(16) float sx[4][128];

    const int total = TT * BB;
    const int chunk = (total + gridDim.x - 1) / gridDim.x;
    const int m0 = blockIdx.x * chunk;
    const int m1 = (m0 + chunk < total) ? (m0 + chunk) : total;

    for (int m = m0; m < m1; m += 4) {
        const int nr = (m1 - m < 4) ? (m1 - m) : 4;
        for (int i = j; i < nr * 128; i += 384) {
            const int r = i >> 7, c = i & 127;
            const int mm = m + r;
            const float* src;
            if (mode == 0) {
                const int t = mm >> 6, b = mm & 63;
                src = X + ((size_t)b * TT + t) * DD;
            } else {
                src = g_h0 + (size_t)mm * HH;
            }
            sx[r][c] = src[c];
        }
        __syncthreads();

        u64 a0 = f2u(bj, 0.f), a1 = f2u(bj, 0.f), a2 = f2u(bj, 0.f), a3 = f2u(bj, 0.f);
        u64 b0 = 0, b1 = 0, b2 = 0, b3 = 0;
        const ulonglong2* r0 = (const ulonglong2*)sx[0];
        const ulonglong2* r1 = (const ulonglong2*)sx[1];
        const ulonglong2* r2 = (const ulonglong2*)sx[2];
        const ulonglong2* r3 = (const ulonglong2*)sx[3];
        #pragma unroll
        for (int k = 0; k < 32; k++) {
            ulonglong2 v0 = r0[k], v1 = r1[k], v2 = r2[k], v3 = r3[k];
            fma2(a0, v0.x, w[2*k]); fma2(b0, v0.y, w[2*k+1]);
            fma2(a1, v1.x, w[2*k]); fma2(b1, v1.y, w[2*k+1]);
            fma2(a2, v2.x, w[2*k]); fma2(b2, v2.y, w[2*k+1]);
            fma2(a3, v3.x, w[2*k]); fma2(b3, v3.y, w[2*k+1]);
        }
        if (nr > 0) g_gi[(size_t)(m + 0) * GG + j] = hsum(a0, b0);
        if (nr > 1) g_gi[(size_t)(m + 1) * GG + j] = hsum(a1, b1);
        if (nr > 2) g_gi[(size_t)(m + 2) * GG + j] = hsum(a2, b2);
        if (nr > 3) g_gi[(size_t)(m + 3) * GG + j] = hsum(a3, b3);
        __syncthreads();
    }
}

// ---------------------------------------------------------------------------
// Sequential GRU recurrence, one CTA per batch element.
// Roles: threads   0-127 : r-gate rows + ALL gate math (r kept in registers)
//        threads 128-255 : z-gate rows (STS acc+gi_z)
//        threads 256-383 : n-gate rows (STS acc)
// Sync:  workers: bar.arrive(1) -> bar.sync(2)     (never wait on gate chain start)
//        gates:   bar.sync(1) -> gates, STS h -> bar.arrive(2) -> bar.sync(3,128)
// ---------------------------------------------------------------------------
__global__ __launch_bounds__(384, 1) void gru_rec(
    const float* __restrict__ Whh,
    const float* __restrict__ bhh,
    int store_h0,
    float* __restrict__ hout)
{
    const int j = threadIdx.x;
    const int b = blockIdx.x;

    u64 w[64];
    {
        const ulonglong2* wr = (const ulonglong2*)(Whh + (size_t)j * 128);
        #pragma unroll
        for (int k = 0; k < 32; k++) { ulonglong2 v = wr[k]; w[2*k] = v.x; w[2*k+1] = v.y; }
    }
    const float bj = bhh[j];

    __shared__ __align__(16) float s_h[128];
    __shared__ float s_zn[256];   // [0:128)=gh_z+gi_z (pre-sigmoid), [128:256)=gh_n

    if (j < 128) s_h[j] = 0.0f;
    __syncthreads();

    const size_t S = (size_t)BB * GG;               // gi stride per timestep
    const float* gbase = g_gi + (size_t)b * GG;

    const ulonglong2* h16 = (const ulonglong2*)s_h;

    if (j < 128) {
        // ---------------- gate warps ----------------
        const float* pr = gbase + j;        // gi_r stream
        const float* pn = gbase + 256 + j;  // gi_n stream
        float gr_c = pr[0],  gr_n1 = pr[S];
        float gn_c = pn[0],  gn_n1 = pn[S];
        float hreg = 0.0f;
        float* h0p = g_h0 + (size_t)b * HH + j;

        for (int t = 0; t < TT; t++) {
            // prefetch t+2 (two full steps of cover)
            float gr_f = 0.f, gn_f = 0.f;
            if (t + 2 < TT) {
                gr_f = pr[(size_t)(t + 2) * S];
                gn_f = pn[(size_t)(t + 2) * S];
            }

            u64 a0 = f2u(bj, 0.f), a1 = 0;
            #pragma unroll
            for (int k = 0; k < 32; k++) {
                ulonglong2 hv = h16[k];
                fma2(a0, hv.x, w[2*k]);
                fma2(a1, hv.y, w[2*k+1]);
            }
            const float accr = hsum(a0, a1);
            const float r = fsig(accr + gr_c);       // register-only, pre-barrier

            bar_sync(1, 384);                        // wait z/n rows
            const float ghz = s_zn[j];
            const float ghn = s_zn[j + 128];
            const float z  = fsig(ghz);
            const float n  = ftanh(gn_c + r * ghn);
            const float hn = n + z * (hreg - n);
            s_h[j] = hn;
            hreg   = hn;
            if (store_h0) h0p[(size_t)t * BB * HH] = hn;
            bar_arrive(2, 384);                      // publish h to workers
            bar_sync(3, 128);                        // gate-warp-internal h visibility

            gr_c = gr_n1; gr_n1 = gr_f;
            gn_c = gn_n1; gn_n1 = gn_f;
        }
        hout[(size_t)b * HH + j] = hreg;
    } else {
        // ---------------- worker warps (z rows: 128-255, n rows: 256-383) ----
        const bool isZ = (j < 256);
        const float* pg = gbase + j;        // gi_z stream (n rows never read gi)
        float g_c = 0.f, g_n1 = 0.f;
        if (isZ) { g_c = pg[0]; g_n1 = pg[S]; }

        for (int t = 0; t < TT; t++) {
            float g_f = 0.f;
            if (isZ && t + 2 < TT) g_f = pg[(size_t)(t + 2) * S];

            u64 a0 = f2u(bj, 0.f), a1 = 0;
            #pragma unroll
            for (int k = 0; k < 32; k++) {
                ulonglong2 hv = h16[k];
                fma2(a0, hv.x, w[2*k]);
                fma2(a1, hv.y, w[2*k+1]);
            }
            const float acc = hsum(a0, a1);
            s_zn[j - 128] = isZ ? (acc + g_c) : acc;

            bar_arrive(1, 384);                      // signal gh row ready
            bar_sync(2, 384);                        // wait for new h

            g_c = g_n1; g_n1 = g_f;
        }
    }
}

extern "C" void kernel_launch(void* const* d_in, const int* in_sizes, int n_in,
                              void* d_out, int out_size)
{
    const float* x     = (const float*)d_in[0];
    const float* W_ih0 = (const float*)d_in[1];
    const float* W_hh0 = (const float*)d_in[2];
    const float* b_ih0 = (const float*)d_in[3];
    const float* b_hh0 = (const float*)d_in[4];
    const float* W_ih1 = (const float*)d_in[5];
    const float* W_hh1 = (const float*)d_in[6];
    const float* b_ih1 = (const float*)d_in[7];
    const float* b_hh1 = (const float*)d_in[8];
    float* out = (float*)d_out;   // [L=2, B, H]

    gi_gemm<<<148, 384>>>(x, W_ih0, b_ih0, /*mode=*/0);
    gru_rec<<<BB, 384>>>(W_hh0, b_hh0, /*store_h0=*/1, out);
    gi_gemm<<<148, 384>>>(nullptr, W_ih1, b_ih1, /*mode=*/1);
    gru_rec<<<BB, 384>>>(W_hh1, b_hh1, /*store_h0=*/0, out + BB * HH);
}

// round 4
// speedup vs baseline: 1.0988x; 1.0988x over previous
#include <cuda_runtime.h>

#define BB 64
#define TT 4096
#define DD 128
#define HH 128
#define GG 384            // 3*H, gates [r, z, n]

#define N_REC 32          // rec CTAs per layer, 2 batches each
#define N_G   42          // gemm CTAs per layer
// roles: [0,32) rec0, [32,64) rec1, [64,106) gemm0, [106,148) gemm1

typedef unsigned long long u64;

// Scratch (device globals — no allocation allowed).
__device__ float g_gi0[(size_t)TT * BB * GG];
__device__ float g_gi1[(size_t)TT * BB * GG];
__device__ float g_h0 [(size_t)TT * BB * HH];
__device__ unsigned g_f_gi0[TT];   // gi0[t] ready (target 1)
__device__ unsigned g_f_h0 [TT];   // h0[t] ready  (target N_REC)
__device__ unsigned g_f_gi1[TT];   // gi1[t] ready (target 1)

// ---- packed f32x2 + activation helpers -----------------------------------
__device__ __forceinline__ void fma2(u64& d, u64 a, u64 b) {
    asm("fma.rn.f32x2 %0, %1, %2, %0;" : "+l"(d) : "l"(a), "l"(b));
}
__device__ __forceinline__ u64 f2u(float x, float y) {
    u64 v; asm("mov.b64 %0, {%1,%2};" : "=l"(v) : "f"(x), "f"(y)); return v;
}
__device__ __forceinline__ float sum2(u64 v) {
    float lo, hi; asm("mov.b64 {%0,%1}, %2;" : "=f"(lo), "=f"(hi) : "l"(v));
    return lo + hi;
}
__device__ __forceinline__ float fsig(float x) {
    return __fdividef(1.0f, 1.0f + __expf(-x));
}
__device__ __forceinline__ float ftanh(float x) {
    return 1.0f - __fdividef(2.0f, __expf(2.0f * x) + 1.0f);
}

// ---- flag primitives (gpu-scope release/acquire) -------------------------
__device__ __forceinline__ unsigned ld_acq(const unsigned* p) {
    unsigned v;
    asm volatile("ld.acquire.gpu.global.b32 %0, [%1];" : "=r"(v) : "l"(p));
    return v;
}
__device__ __forceinline__ void red_rel(unsigned* p) {
    asm volatile("red.release.gpu.global.add.u32 [%0], 1;" :: "l"(p) : "memory");
}
__device__ __forceinline__ void spin_ge(const unsigned* p, unsigned target) {
    while (ld_acq(p) < target) { __nanosleep(64); }
}

__global__ void zero_flags() {
    int i = blockIdx.x * blockDim.x + threadIdx.x;
    if (i < TT) { g_f_gi0[i] = 0; g_f_h0[i] = 0; g_f_gi1[i] = 0; }
}

// ---------------------------------------------------------------------------
// Shared memory (union of roles)
// ---------------------------------------------------------------------------
struct SmemRec {
    float h[2][128];      // hidden state, both batches (16B-aligned)
    float gh[2][384];     // pre-activation gh (+gi for r,z rows)
};
struct SmemGemm {
    float x[4][128];      // 4 staged activation rows
};
union SmemAll { SmemRec r; SmemGemm g; };

// ---------------------------------------------------------------------------
// GEMM role: stream gi[t] = act_row @ W^T + bias for t = t0, t0+N_G, ...
//   which=0: act rows = x[b][t][:]  (no dependency)
//   which=1: act rows = h0[t][b][:] (wait g_f_h0[t] == N_REC)
// ---------------------------------------------------------------------------
__device__ void gemm_role(SmemAll* sm,
                          const float* __restrict__ X,
                          const float* __restrict__ W,
                          const float* __restrict__ bias,
                          int which, int t0)
{
    const int j = threadIdx.x;

    u64 w[64];
    {
        const ulonglong2* wr = (const ulonglong2*)(W + (size_t)j * 128);
        #pragma unroll
        for (int k = 0; k < 32; k++) { ulonglong2 v = wr[k]; w[2*k] = v.x; w[2*k+1] = v.y; }
    }
    const float bj = bias[j];
    float* dst = which ? g_gi1 : g_gi0;
    unsigned* fout = which ? g_f_gi1 : g_f_gi0;

    for (int t = t0; t < TT; t += N_G) {
        if (which == 1) {
            if (j == 0) spin_ge(&g_f_h0[t], N_REC);
        }
        __syncthreads();

        for (int m = 0; m < BB; m += 4) {
            // stage 4 activation rows
            for (int i = j; i < 4 * 128; i += 384) {
                const int r = i >> 7, c = i & 127;
                const int b = m + r;
                const float* src = which
                    ? (g_h0 + ((size_t)t * BB + b) * HH)
                    : (X + ((size_t)b * TT + t) * DD);
                sm->g.x[r][c] = src[c];
            }
            __syncthreads();

            u64 a0 = f2u(bj, 0.f), a1 = f2u(bj, 0.f), a2 = f2u(bj, 0.f), a3 = f2u(bj, 0.f);
            const ulonglong2* r0 = (const ulonglong2*)sm->g.x[0];
            const ulonglong2* r1 = (const ulonglong2*)sm->g.x[1];
            const ulonglong2* r2 = (const ulonglong2*)sm->g.x[2];
            const ulonglong2* r3 = (const ulonglong2*)sm->g.x[3];
            #pragma unroll
            for (int k = 0; k < 32; k++) {
                ulonglong2 v0 = r0[k], v1 = r1[k], v2 = r2[k], v3 = r3[k];
                fma2(a0, v0.x, w[2*k]); fma2(a0, v0.y, w[2*k+1]);
                fma2(a1, v1.x, w[2*k]); fma2(a1, v1.y, w[2*k+1]);
                fma2(a2, v2.x, w[2*k]); fma2(a2, v2.y, w[2*k+1]);
                fma2(a3, v3.x, w[2*k]); fma2(a3, v3.y, w[2*k+1]);
            }
            dst[((size_t)t * BB + m + 0) * GG + j] = sum2(a0);
            dst[((size_t)t * BB + m + 1) * GG + j] = sum2(a1);
            dst[((size_t)t * BB + m + 2) * GG + j] = sum2(a2);
            dst[((size_t)t * BB + m + 3) * GG + j] = sum2(a3);
            __syncthreads();
        }
        if (j == 0) red_rel(&fout[t]);
    }
}

// ---------------------------------------------------------------------------
// REC role: sequential GRU for 2 batches (b0=2c, b1=2c+1), sharing W_hh regs.
// Thread j owns gate-row j for BOTH batches. Threads 0-255 do gate math for
// (batch j>>7, elem j&127). Layer 0 publishes h0[t] + flag each step.
// ---------------------------------------------------------------------------
__device__ void rec_role(SmemAll* sm,
                         const float* __restrict__ Whh,
                         const float* __restrict__ bhh,
                         int layer, int c,
                         float* __restrict__ hout)
{
    const int j = threadIdx.x;
    const int b0 = 2 * c, b1 = 2 * c + 1;

    u64 w[64];
    {
        const ulonglong2* wr = (const ulonglong2*)(Whh + (size_t)j * 128);
        #pragma unroll
        for (int k = 0; k < 32; k++) { ulonglong2 v = wr[k]; w[2*k] = v.x; w[2*k+1] = v.y; }
    }
    const float bj = bhh[j];

    const float* gi = layer ? g_gi1 : g_gi0;
    const unsigned* fin = layer ? g_f_gi1 : g_f_gi0;

    const size_t S = (size_t)BB * GG;
    const bool isRZ = (j < 256);
    const int e  = j & 127;
    const int bl = (j >> 7) & 1;           // gate threads: local batch
    const int bglob = 2 * c + bl;

    const float* gp0 = gi + (size_t)b0 * GG + j;        // row gi streams (r,z rows)
    const float* gp1 = gi + (size_t)b1 * GG + j;
    const float* pn  = gi + (size_t)bglob * GG + 256 + e; // gate thread: gi_n stream
    float* h0p = g_h0 + (size_t)bglob * HH + e;           // layer-0 h store

    if (j < 128) { sm->r.h[0][j] = 0.0f; sm->r.h[1][j] = 0.0f; }
    if (j == 0) spin_ge(&fin[0], 1);
    __syncthreads();

    float gA = isRZ ? gp0[0] : 0.0f;
    float gB = isRZ ? gp1[0] : 0.0f;
    float gN = (j < 256) ? pn[0] : 0.0f;
    float hreg = 0.0f;

    for (int t = 0; t < TT; t++) {
        // --- dual-batch dot: gh row j for b0 and b1 (shared weights) ---
        u64 a0 = f2u(bj, 0.f), a1 = f2u(bj, 0.f);
        const ulonglong2* h0v = (const ulonglong2*)sm->r.h[0];
        const ulonglong2* h1v = (const ulonglong2*)sm->r.h[1];
        #pragma unroll
        for (int k = 0; k < 32; k++) {
            ulonglong2 v0 = h0v[k], v1 = h1v[k];
            fma2(a0, v0.x, w[2*k]); fma2(a0, v0.y, w[2*k+1]);
            fma2(a1, v1.x, w[2*k]); fma2(a1, v1.y, w[2*k+1]);
        }
        sm->r.gh[0][j] = sum2(a0) + (isRZ ? gA : 0.0f);
        sm->r.gh[1][j] = sum2(a1) + (isRZ ? gB : 0.0f);
        __syncthreads();                       // (A) gh ready

        // spare thread pre-verifies next step's gi flag during gate phase
        if (j == 383 && t + 1 < TT) spin_ge(&fin[t + 1], 1);

        if (j < 256) {
            const float gr  = sm->r.gh[bl][e];
            const float gz  = sm->r.gh[bl][e + 128];
            const float ghn = sm->r.gh[bl][e + 256];
            const float r = fsig(gr);
            const float z = fsig(gz);
            const float n = ftanh(gN + r * ghn);
            hreg = n + z * (hreg - n);
            sm->r.h[bl][e] = hreg;
            if (layer == 0) h0p[(size_t)t * BB * HH] = hreg;
        }
        __syncthreads();                       // (B) h published, flag known ready
        if (layer == 0 && j == 0) red_rel(&g_f_h0[t]);

        if (t + 1 < TT) {
            const size_t off = (size_t)(t + 1) * S;
            if (isRZ) { gA = gp0[off]; gB = gp1[off]; }
            if (j < 256) gN = pn[off];
        }
    }

    if (j < 256) hout[(size_t)bglob * HH + e] = hreg;
}

// ---------------------------------------------------------------------------
__global__ __launch_bounds__(384, 1) void gru_fused(
    const float* __restrict__ x,
    const float* __restrict__ W_ih0, const float* __restrict__ W_hh0,
    const float* __restrict__ b_ih0, const float* __restrict__ b_hh0,
    const float* __restrict__ W_ih1, const float* __restrict__ W_hh1,
    const float* __restrict__ b_ih1, const float* __restrict__ b_hh1,
    float* __restrict__ out)
{
    __shared__ __align__(16) SmemAll sm;
    const int bid = blockIdx.x;

    if (bid < N_REC) {
        rec_role(&sm, W_hh0, b_hh0, /*layer=*/0, bid, out);
    } else if (bid < 2 * N_REC) {
        rec_role(&sm, W_hh1, b_hh1, /*layer=*/1, bid - N_REC, out + BB * HH);
    } else if (bid < 2 * N_REC + N_G) {
        gemm_role(&sm, x, W_ih0, b_ih0, /*which=*/0, bid - 2 * N_REC);
    } else {
        gemm_role(&sm, nullptr, W_ih1, b_ih1, /*which=*/1, bid - 2 * N_REC - N_G);
    }
}

extern "C" void kernel_launch(void* const* d_in, const int* in_sizes, int n_in,
                              void* d_out, int out_size)
{
    const float* x     = (const float*)d_in[0];
    const float* W_ih0 = (const float*)d_in[1];
    const float* W_hh0 = (const float*)d_in[2];
    const float* b_ih0 = (const float*)d_in[3];
    const float* b_hh0 = (const float*)d_in[4];
    const float* W_ih1 = (const float*)d_in[5];
    const float* W_hh1 = (const float*)d_in[6];
    const float* b_ih1 = (const float*)d_in[7];
    const float* b_hh1 = (const float*)d_in[8];
    float* out = (float*)d_out;   // [L=2, B, H]

    zero_flags<<<(TT + 255) / 256, 256>>>();
    gru_fused<<<2 * N_REC + 2 * N_G, 384>>>(
        x, W_ih0, W_hh0, b_ih0, b_hh0, W_ih1, W_hh1, b_ih1, b_hh1, out);
}